// round 1
// baseline (speedup 1.0000x reference)
#include <cuda_runtime.h>
#include <math.h>
#include <stdint.h>

// HashGrid2D: N=1e6 points, 16 levels, T=2^19, 2 hashgrids, feature dim 2.
// One thread per (point, level). 4 random float2 gathers per thread, bilinear
// blend, coalesced float2 store.

#define N_LEVELS 16
#define TBITS 19
#define TSIZE (1u << TBITS)
#define PRIME_Y 2654435761u

struct ScaleArr {
    float s[N_LEVELS];
};

__global__ void __launch_bounds__(256) hashgrid2d_kernel(
    const float2* __restrict__ x,        // [N] (x,y)
    const float2* __restrict__ feat,     // [2,16,T] of float2
    const int*    __restrict__ gidx,     // [N]
    float2*       __restrict__ out,      // [N,16] float2 == [N,32] float
    int n_total,                         // N * 16
    ScaleArr sc)
{
    int t = blockIdx.x * blockDim.x + threadIdx.x;
    if (t >= n_total) return;

    int level = t & (N_LEVELS - 1);
    int p     = t >> 4;

    float2 xy = __ldg(&x[p]);
    int g     = __ldg(&gidx[p]);

    float s  = sc.s[level];
    float px = xy.x * s;
    float py = xy.y * s;
    float fx = floorf(px);
    float fy = floorf(py);
    float wx = px - fx;
    float wy = py - fy;

    unsigned ix = (unsigned)(int)fx;
    unsigned iy = (unsigned)(int)fy;

    const float2* __restrict__ base = feat + ((size_t)(g * N_LEVELS + level) << TBITS);

    unsigned hy0 = iy * PRIME_Y;
    unsigned hy1 = (iy + 1u) * PRIME_Y;
    unsigned h00 = ( ix        ^ hy0) & (TSIZE - 1u);
    unsigned h10 = ((ix + 1u)  ^ hy0) & (TSIZE - 1u);
    unsigned h01 = ( ix        ^ hy1) & (TSIZE - 1u);
    unsigned h11 = ((ix + 1u)  ^ hy1) & (TSIZE - 1u);

    // 4 independent gathers -> MLP=4 per thread
    float2 f00 = __ldg(base + h00);
    float2 f10 = __ldg(base + h10);
    float2 f01 = __ldg(base + h01);
    float2 f11 = __ldg(base + h11);

    float w00 = (1.0f - wx) * (1.0f - wy);
    float w10 = wx * (1.0f - wy);
    float w01 = (1.0f - wx) * wy;
    float w11 = wx * wy;

    float2 o;
    o.x = w00 * f00.x + w10 * f10.x + w01 * f01.x + w11 * f11.x;
    o.y = w00 * f00.y + w10 * f10.y + w01 * f01.y + w11 * f11.y;

    out[t] = o;
}

extern "C" void kernel_launch(void* const* d_in, const int* in_sizes, int n_in,
                              void* d_out, int out_size)
{
    const float2* x    = (const float2*)d_in[0];       // [N,2] f32
    const float2* feat = (const float2*)d_in[1];       // [2,16,T,2] f32
    const int*    gidx = (const int*)d_in[2];          // [N,1] i32
    float2*       out  = (float2*)d_out;               // [N,32] f32

    int N = in_sizes[0] / 2;
    int n_total = N * N_LEVELS;

    // Per-level scale = (res - 1), res computed with the exact same libm
    // double math as the Python reference (math.exp/log, b**i via pow).
    ScaleArr sc;
    double bw = exp((log(512.0) - log(16.0)) / (double)(N_LEVELS - 1));
    for (int i = 0; i < N_LEVELS; i++) {
        int res = (int)(16.0 * pow(bw, (double)i));
        sc.s[i] = (float)(res - 1);
    }

    int threads = 256;
    int blocks  = (n_total + threads - 1) / threads;
    hashgrid2d_kernel<<<blocks, threads>>>(x, feat, gidx, out, n_total, sc);
}